// round 5
// baseline (speedup 1.0000x reference)
#include <cuda_runtime.h>
#include <cuda_bf16.h>
#include <cstdint>

#define HEADS 32
#define SEQ   2048
#define DH    128
#define BM    128
#define BN    64
#define NIT   (SEQ / BN)
#define NT    256
#define NELEM (HEADS * SEQ * DH)

// bf16 hi/lo scratch (device globals: sanctioned scratch, no allocs)
__device__ __align__(16) unsigned short g_qhi[NELEM];
__device__ __align__(16) unsigned short g_qlo[NELEM];
__device__ __align__(16) unsigned short g_khi[NELEM];
__device__ __align__(16) unsigned short g_klo[NELEM];
__device__ __align__(16) unsigned short g_vhi[NELEM];   // V^T [head][d][s]
__device__ __align__(16) unsigned short g_vlo[NELEM];

// smem byte offsets
#define OFF_QH  0u
#define OFF_QL  32768u
#define OFF_STG 65536u
#define STG_SZ  65536u
#define S_KH    0u
#define S_KL    16384u
#define S_VH    32768u
#define S_VL    49152u
#define SMEM_MAIN (OFF_STG + 2 * STG_SZ)   // 192KB

// ---------------- PTX helpers ----------------
__device__ __forceinline__ uint32_t smem_u32(const void* p) {
    uint32_t a;
    asm("{ .reg .u64 t; cvta.to.shared.u64 t, %1; cvt.u32.u64 %0, t; }" : "=r"(a) : "l"(p));
    return a;
}
__device__ __forceinline__ void cp16(uint32_t dst, const void* src) {
    asm volatile("cp.async.cg.shared.global [%0], [%1], 16;" :: "r"(dst), "l"(src) : "memory");
}
#define CP_COMMIT() asm volatile("cp.async.commit_group;" ::: "memory")
#define CP_WAIT_1() asm volatile("cp.async.wait_group 1;" ::: "memory")
#define CP_WAIT_0() asm volatile("cp.async.wait_group 0;" ::: "memory")

#define LDSM4(r, a) \
    asm volatile("ldmatrix.sync.aligned.m8n8.x4.shared.b16 {%0,%1,%2,%3}, [%4];" \
        : "=r"((r)[0]), "=r"((r)[1]), "=r"((r)[2]), "=r"((r)[3]) : "r"(a))

#define MMA(c, a, b0, b1) \
    asm volatile("mma.sync.aligned.m16n8k16.row.col.f32.bf16.bf16.f32 " \
        "{%0,%1,%2,%3}, {%4,%5,%6,%7}, {%8,%9}, {%0,%1,%2,%3};" \
        : "+f"((c)[0]), "+f"((c)[1]), "+f"((c)[2]), "+f"((c)[3]) \
        : "r"((a)[0]), "r"((a)[1]), "r"((a)[2]), "r"((a)[3]), "r"(b0), "r"(b1))

__device__ __forceinline__ uint32_t pack_lo_bf16x2(float x, float y) {
    uint32_t d;
    asm("cvt.rn.bf16x2.f32 %0, %1, %2;" : "=r"(d) : "f"(y), "f"(x));
    return d;
}

// ---------------- hi/lo split ----------------
__device__ __forceinline__ void split1(float v, unsigned short& h, unsigned short& l) {
    uint32_t b = __float_as_uint(v);
    h = (unsigned short)(b >> 16);
    float r = v - __uint_as_float(b & 0xffff0000u);
    l = __bfloat16_as_ushort(__float2bfloat16(r));
}

__global__ void split_qk_kernel(const float4* __restrict__ Q, const float4* __restrict__ K,
                                unsigned short* __restrict__ qh, unsigned short* __restrict__ ql,
                                unsigned short* __restrict__ kh, unsigned short* __restrict__ kl,
                                int n4) {
    for (int i = blockIdx.x * blockDim.x + threadIdx.x; i < n4; i += gridDim.x * blockDim.x) {
        unsigned short h0,h1,h2,h3,l0,l1,l2,l3;
        float4 q = Q[i];
        split1(q.x,h0,l0); split1(q.y,h1,l1); split1(q.z,h2,l2); split1(q.w,h3,l3);
        *reinterpret_cast<uint2*>(qh + 4*(size_t)i) =
            make_uint2((uint32_t)h0 | ((uint32_t)h1<<16), (uint32_t)h2 | ((uint32_t)h3<<16));
        *reinterpret_cast<uint2*>(ql + 4*(size_t)i) =
            make_uint2((uint32_t)l0 | ((uint32_t)l1<<16), (uint32_t)l2 | ((uint32_t)l3<<16));
        float4 k = K[i];
        split1(k.x,h0,l0); split1(k.y,h1,l1); split1(k.z,h2,l2); split1(k.w,h3,l3);
        *reinterpret_cast<uint2*>(kh + 4*(size_t)i) =
            make_uint2((uint32_t)h0 | ((uint32_t)h1<<16), (uint32_t)h2 | ((uint32_t)h3<<16));
        *reinterpret_cast<uint2*>(kl + 4*(size_t)i) =
            make_uint2((uint32_t)l0 | ((uint32_t)l1<<16), (uint32_t)l2 | ((uint32_t)l3<<16));
    }
}

__global__ void v_transpose_split_kernel(const float* __restrict__ V,
                                         unsigned short* __restrict__ vh,
                                         unsigned short* __restrict__ vl) {
    __shared__ float t[32][33];
    int h = blockIdx.z, s0 = blockIdx.x * 32, d0 = blockIdx.y * 32;
    int tx = threadIdx.x, ty = threadIdx.y;
    const float* src = V + ((size_t)h * SEQ + s0) * DH + d0;
#pragma unroll
    for (int j = 0; j < 32; j += 8)
        t[ty + j][tx] = src[(size_t)(ty + j) * DH + tx];
    __syncthreads();
#pragma unroll
    for (int j = 0; j < 32; j += 8) {
        unsigned short hh, ll;
        split1(t[tx][ty + j], hh, ll);
        size_t o = ((size_t)h * DH + d0 + ty + j) * SEQ + s0 + tx;
        vh[o] = hh; vl[o] = ll;
    }
}

// ---------------- stage loader (cp.async, swizzled) ----------------
__device__ __forceinline__ void stage_load(uint32_t stg,
                                           const unsigned short* gkh, const unsigned short* gkl,
                                           const unsigned short* gvh, const unsigned short* gvl,
                                           int tid) {
#pragma unroll
    for (int t = 0; t < 4; ++t) {
        int idx = tid + t * NT;
        int r = idx >> 4, c16 = idx & 15;
        uint32_t d = stg + S_KH + ((uint32_t)r << 8) + (uint32_t)((c16 ^ (r & 7)) << 4);
        cp16(d, gkh + (size_t)r * DH + c16 * 8);
        cp16(d + (S_KL - S_KH), gkl + (size_t)r * DH + c16 * 8);
    }
#pragma unroll
    for (int t = 0; t < 4; ++t) {
        int idx = tid + t * NT;
        int r = idx >> 3, c16 = idx & 7;
        uint32_t d = stg + S_VH + ((uint32_t)r << 7) + (uint32_t)((c16 ^ (r & 7)) << 4);
        cp16(d, gvh + (size_t)r * SEQ + c16 * 8);
        cp16(d + (S_VL - S_VH), gvl + (size_t)r * SEQ + c16 * 8);
    }
}

// ---------------- main attention kernel ----------------
// Warps: wm = warp&3 (32 query rows), wn = warp>>2 (32 keys of the 64-key tile).
__global__ __launch_bounds__(NT, 1)
void fa_hmma_kernel(float* __restrict__ Out) {
    extern __shared__ char smc[];
    const uint32_t sb = smem_u32(smc);
    const int tid  = threadIdx.x;
    const int lane = tid & 31;
    const int warp = tid >> 5;
    const int wm   = warp & 3;
    const int wn   = warp >> 2;
    const int head = blockIdx.y;
    const int q0   = blockIdx.x * BM;
    const size_t base = (size_t)head * SEQ * DH;

    const unsigned short* gqh = g_qhi + base + (size_t)q0 * DH;
    const unsigned short* gql = g_qlo + base + (size_t)q0 * DH;
    const unsigned short* gkh0 = g_khi + base;
    const unsigned short* gkl0 = g_klo + base;
    const unsigned short* gvh0 = g_vhi + (size_t)head * DH * SEQ;
    const unsigned short* gvl0 = g_vlo + (size_t)head * DH * SEQ;

    stage_load(sb + OFF_STG, gkh0, gkl0, gvh0, gvl0, tid);
    CP_COMMIT();
    stage_load(sb + OFF_STG + STG_SZ, gkh0 + BN * DH, gkl0 + BN * DH,
               gvh0 + BN, gvl0 + BN, tid);
    CP_COMMIT();

    for (int idx = tid; idx < 2048; idx += NT) {
        int r = idx >> 4, c16 = idx & 15;
        uint32_t d = ((uint32_t)r << 8) + (uint32_t)((c16 ^ (r & 7)) << 4);
        *reinterpret_cast<uint4*>(smc + OFF_QH + d) =
            *reinterpret_cast<const uint4*>(gqh + (size_t)r * DH + c16 * 8);
        *reinterpret_cast<uint4*>(smc + OFF_QL + d) =
            *reinterpret_cast<const uint4*>(gql + (size_t)r * DH + c16 * 8);
    }

    // ldmatrix lane geometry
    const int r0    = wm * 32;
    const int a_row = r0 + (lane & 7) + ((lane >> 3) & 1) * 8;  // rg adds +16
    const int a_c8  = lane >> 4;
    const int axr   = a_row & 7;
    const int b_row = (lane & 7) + ((lane >> 4) << 3);
    const int b_c8  = (lane >> 3) & 1;
    const int bxr   = b_row & 7;

    float co[32][4];
#pragma unroll
    for (int i = 0; i < 32; ++i)
#pragma unroll
        for (int j = 0; j < 4; ++j) co[i][j] = 0.0f;
    float ls[4] = {0.0f, 0.0f, 0.0f, 0.0f};   // [rg*2 + rowhalf]

    for (int i = 0; i < NIT; ++i) {
        const uint32_t stg = sb + OFF_STG + (uint32_t)(i & 1) * STG_SZ;
        if (i == NIT - 1) { CP_WAIT_0(); } else { CP_WAIT_1(); }
        __syncthreads();

        // ---- S = Q K^T : 32 rows x 32 keys per warp, 3-product hi/lo ----
        float cs[8][4];
#pragma unroll
        for (int t = 0; t < 8; ++t)
#pragma unroll
            for (int j = 0; j < 4; ++j) cs[t][j] = 0.0f;

#pragma unroll
        for (int ks = 0; ks < 8; ++ks) {
            uint32_t qh0[4], ql0[4], qh1[4], ql1[4];
            uint32_t aaddr = sb + OFF_QH + (uint32_t)(a_row << 8) +
                             (uint32_t)(((2 * ks + a_c8) ^ axr) << 4);
            LDSM4(qh0, aaddr);
            LDSM4(ql0, aaddr + (OFF_QL - OFF_QH));
            LDSM4(qh1, aaddr + (16 << 8));
            LDSM4(ql1, aaddr + (16 << 8) + (OFF_QL - OFF_QH));
#pragma unroll
            for (int n2 = 0; n2 < 2; ++n2) {
                uint32_t kh[4], kl[4];
                uint32_t baddr = stg + S_KH +
                                 (uint32_t)((wn * 32 + n2 * 16 + b_row) << 8) +
                                 (uint32_t)(((2 * ks + b_c8) ^ bxr) << 4);
                LDSM4(kh, baddr);
                LDSM4(kl, baddr + (S_KL - S_KH));
                MMA(cs[n2 * 2],     qh0, kh[0], kh[1]);
                MMA(cs[n2 * 2 + 1], qh0, kh[2], kh[3]);
                MMA(cs[n2 * 2],     qh0, kl[0], kl[1]);
                MMA(cs[n2 * 2 + 1], qh0, kl[2], kl[3]);
                MMA(cs[n2 * 2],     ql0, kh[0], kh[1]);
                MMA(cs[n2 * 2 + 1], ql0, kh[2], kh[3]);
                MMA(cs[4 + n2 * 2],     qh1, kh[0], kh[1]);
                MMA(cs[4 + n2 * 2 + 1], qh1, kh[2], kh[3]);
                MMA(cs[4 + n2 * 2],     qh1, kl[0], kl[1]);
                MMA(cs[4 + n2 * 2 + 1], qh1, kl[2], kl[3]);
                MMA(cs[4 + n2 * 2],     ql1, kh[0], kh[1]);
                MMA(cs[4 + n2 * 2 + 1], ql1, kh[2], kh[3]);
            }
        }

        // ---- softmax (no max: logits bounded ~65 < fp32 exp range) ----
        uint32_t ph[2][2][4], pl[2][2][4];
#pragma unroll
        for (int rg = 0; rg < 2; ++rg) {
#pragma unroll
            for (int j = 0; j < 2; ++j) {
                float* ca = cs[rg * 4 + j * 2];
                float* cb = cs[rg * 4 + j * 2 + 1];
                float e0 = __expf(ca[0]), e1 = __expf(ca[1]);
                float e2 = __expf(ca[2]), e3 = __expf(ca[3]);
                float e4 = __expf(cb[0]), e5 = __expf(cb[1]);
                float e6 = __expf(cb[2]), e7 = __expf(cb[3]);
                ls[rg * 2 + 0] += (e0 + e1) + (e4 + e5);
                ls[rg * 2 + 1] += (e2 + e3) + (e6 + e7);
                uint32_t u0 = __float_as_uint(e0), u1 = __float_as_uint(e1);
                uint32_t u2 = __float_as_uint(e2), u3 = __float_as_uint(e3);
                uint32_t u4 = __float_as_uint(e4), u5 = __float_as_uint(e5);
                uint32_t u6 = __float_as_uint(e6), u7 = __float_as_uint(e7);
                ph[rg][j][0] = __byte_perm(u0, u1, 0x7632);
                ph[rg][j][1] = __byte_perm(u2, u3, 0x7632);
                ph[rg][j][2] = __byte_perm(u4, u5, 0x7632);
                ph[rg][j][3] = __byte_perm(u6, u7, 0x7632);
                pl[rg][j][0] = pack_lo_bf16x2(e0 - __uint_as_float(u0 & 0xffff0000u),
                                              e1 - __uint_as_float(u1 & 0xffff0000u));
                pl[rg][j][1] = pack_lo_bf16x2(e2 - __uint_as_float(u2 & 0xffff0000u),
                                              e3 - __uint_as_float(u3 & 0xffff0000u));
                pl[rg][j][2] = pack_lo_bf16x2(e4 - __uint_as_float(u4 & 0xffff0000u),
                                              e5 - __uint_as_float(u5 & 0xffff0000u));
                pl[rg][j][3] = pack_lo_bf16x2(e6 - __uint_as_float(u6 & 0xffff0000u),
                                              e7 - __uint_as_float(u7 & 0xffff0000u));
            }
        }

        // ---- O += P V over this warp's 32 keys ----
#pragma unroll
        for (int j = 0; j < 2; ++j) {
            const int jj = wn * 2 + j;
#pragma unroll
            for (int n2 = 0; n2 < 8; ++n2) {
                uint32_t vh[4], vl[4];
                uint32_t vaddr = stg + S_VH +
                                 (uint32_t)((n2 * 16 + b_row) << 7) +
                                 (uint32_t)(((2 * jj + b_c8) ^ bxr) << 4);
                LDSM4(vh, vaddr);
                LDSM4(vl, vaddr + (S_VL - S_VH));
#pragma unroll
                for (int rg = 0; rg < 2; ++rg) {
                    MMA(co[rg * 16 + 2 * n2],     ph[rg][j], vh[0], vh[1]);
                    MMA(co[rg * 16 + 2 * n2 + 1], ph[rg][j], vh[2], vh[3]);
                    MMA(co[rg * 16 + 2 * n2],     pl[rg][j], vh[0], vh[1]);
                    MMA(co[rg * 16 + 2 * n2 + 1], pl[rg][j], vh[2], vh[3]);
                    MMA(co[rg * 16 + 2 * n2],     ph[rg][j], vl[0], vl[1]);
                    MMA(co[rg * 16 + 2 * n2 + 1], ph[rg][j], vl[2], vl[3]);
                }
            }
        }

        __syncthreads();
        if (i + 2 < NIT) {
            const int key0 = (i + 2) * BN;
            stage_load(stg, gkh0 + (size_t)key0 * DH, gkl0 + (size_t)key0 * DH,
                       gvh0 + key0, gvl0 + key0, tid);
            CP_COMMIT();
        }
    }

    // ---- epilogue: combine across wn groups, divide by l, store ----
#pragma unroll
    for (int x = 0; x < 4; ++x) {
        ls[x] += __shfl_xor_sync(0xffffffffu, ls[x], 1);
        ls[x] += __shfl_xor_sync(0xffffffffu, ls[x], 2);
    }
    float* lsm = (float*)(smc + OFF_QH);        // lsums[2][128]
    if ((lane & 3) == 0) {
        int rr = lane >> 2;
#pragma unroll
        for (int rg = 0; rg < 2; ++rg)
#pragma unroll
            for (int h = 0; h < 2; ++h)
                lsm[wn * 128 + r0 + rg * 16 + h * 8 + rr] = ls[rg * 2 + h];
    }
    __syncthreads();

    float* osm = (float*)(smc + OFF_STG);       // [128][132] fp32 partial O
    const int orow = lane >> 2;
    const int ocb  = (lane & 3) * 2;
    if (wn == 0) {
#pragma unroll
        for (int idx = 0; idx < 32; ++idx) {
            int rg = idx >> 4, t = idx & 15, n2 = t >> 1, h2 = t & 1;
            int row = r0 + rg * 16 + orow;
            int col = n2 * 16 + h2 * 8 + ocb;
            *reinterpret_cast<float2*>(&osm[row * 132 + col]) =
                make_float2(co[idx][0], co[idx][1]);
            *reinterpret_cast<float2*>(&osm[(row + 8) * 132 + col]) =
                make_float2(co[idx][2], co[idx][3]);
        }
    }
    __syncthreads();
    if (wn == 1) {
        float inv[4];
#pragma unroll
        for (int rg = 0; rg < 2; ++rg)
#pragma unroll
            for (int h = 0; h < 2; ++h) {
                int row = r0 + rg * 16 + h * 8 + orow;
                inv[rg * 2 + h] = 1.0f / (lsm[row] + lsm[128 + row]);
            }
#pragma unroll
        for (int idx = 0; idx < 32; ++idx) {
            int rg = idx >> 4, t = idx & 15, n2 = t >> 1, h2 = t & 1;
            int row = r0 + rg * 16 + orow;
            int col = n2 * 16 + h2 * 8 + ocb;
            float2 p0 = *reinterpret_cast<float2*>(&osm[row * 132 + col]);
            float2 p1 = *reinterpret_cast<float2*>(&osm[(row + 8) * 132 + col]);
            float i0 = inv[rg * 2 + 0], i1 = inv[rg * 2 + 1];
            float2 w0 = make_float2((p0.x + co[idx][0]) * i0, (p0.y + co[idx][1]) * i0);
            float2 w1 = make_float2((p1.x + co[idx][2]) * i1, (p1.y + co[idx][3]) * i1);
            *reinterpret_cast<float2*>(Out + base + (size_t)(q0 + row) * DH + col) = w0;
            *reinterpret_cast<float2*>(Out + base + (size_t)(q0 + row + 8) * DH + col) = w1;
        }
    }
}

extern "C" void kernel_launch(void* const* d_in, const int* in_sizes, int n_in,
                              void* d_out, int out_size) {
    const float* Q = (const float*)d_in[0];
    const float* K = (const float*)d_in[1];
    const float* V = (const float*)d_in[2];
    float* O = (float*)d_out;

    unsigned short *qh, *ql, *kh, *kl, *vh, *vl;
    cudaGetSymbolAddress((void**)&qh, g_qhi);
    cudaGetSymbolAddress((void**)&ql, g_qlo);
    cudaGetSymbolAddress((void**)&kh, g_khi);
    cudaGetSymbolAddress((void**)&kl, g_klo);
    cudaGetSymbolAddress((void**)&vh, g_vhi);
    cudaGetSymbolAddress((void**)&vl, g_vlo);

    split_qk_kernel<<<1024, 256>>>((const float4*)Q, (const float4*)K,
                                   qh, ql, kh, kl, NELEM / 4);
    v_transpose_split_kernel<<<dim3(SEQ / 32, DH / 32, HEADS), dim3(32, 8)>>>(V, vh, vl);

    cudaFuncSetAttribute(fa_hmma_kernel,
                         cudaFuncAttributeMaxDynamicSharedMemorySize, SMEM_MAIN);
    dim3 grid(SEQ / BM, HEADS);
    fa_hmma_kernel<<<grid, NT, SMEM_MAIN>>>(O);
}

// round 6
// speedup vs baseline: 1.0533x; 1.0533x over previous
#include <cuda_runtime.h>
#include <cuda_bf16.h>
#include <cstdint>

#define HEADS 32
#define SEQ   2048
#define DH    128
#define BM    128
#define BN    64
#define NIT   (SEQ / BN)
#define NT    256
#define NELEM (HEADS * SEQ * DH)

// bf16 hi/lo scratch (device globals: sanctioned scratch, no allocs)
__device__ __align__(16) unsigned short g_qhi[NELEM];
__device__ __align__(16) unsigned short g_qlo[NELEM];
__device__ __align__(16) unsigned short g_khi[NELEM];
__device__ __align__(16) unsigned short g_klo[NELEM];
__device__ __align__(16) unsigned short g_vhi[NELEM];   // V^T [head][d][s]
__device__ __align__(16) unsigned short g_vlo[NELEM];

// 3-stage smem ring; inside a stage: KH, KL, VH, VL (16KB each)
#define STG_SZ  65536u
#define S_KH    0u
#define S_KL    16384u
#define S_VH    32768u
#define S_VL    49152u
#define SMEM_MAIN (3u * STG_SZ)   // 192KB

// ---------------- PTX helpers ----------------
__device__ __forceinline__ uint32_t smem_u32(const void* p) {
    uint32_t a;
    asm("{ .reg .u64 t; cvta.to.shared.u64 t, %1; cvt.u32.u64 %0, t; }" : "=r"(a) : "l"(p));
    return a;
}
__device__ __forceinline__ void cp16(uint32_t dst, const void* src) {
    asm volatile("cp.async.cg.shared.global [%0], [%1], 16;" :: "r"(dst), "l"(src) : "memory");
}
#define CP_COMMIT() asm volatile("cp.async.commit_group;" ::: "memory")
#define CP_WAIT_1() asm volatile("cp.async.wait_group 1;" ::: "memory")
#define CP_WAIT_0() asm volatile("cp.async.wait_group 0;" ::: "memory")

#define LDSM4(r, a) \
    asm volatile("ldmatrix.sync.aligned.m8n8.x4.shared.b16 {%0,%1,%2,%3}, [%4];" \
        : "=r"((r)[0]), "=r"((r)[1]), "=r"((r)[2]), "=r"((r)[3]) : "r"(a))

#define MMA(c, a, b0, b1) \
    asm volatile("mma.sync.aligned.m16n8k16.row.col.f32.bf16.bf16.f32 " \
        "{%0,%1,%2,%3}, {%4,%5,%6,%7}, {%8,%9}, {%0,%1,%2,%3};" \
        : "+f"((c)[0]), "+f"((c)[1]), "+f"((c)[2]), "+f"((c)[3]) \
        : "r"((a)[0]), "r"((a)[1]), "r"((a)[2]), "r"((a)[3]), "r"(b0), "r"(b1))

__device__ __forceinline__ uint32_t pack_lo_bf16x2(float x, float y) {
    uint32_t d;
    asm("cvt.rn.bf16x2.f32 %0, %1, %2;" : "=r"(d) : "f"(y), "f"(x));
    return d;
}

// ---------------- hi/lo split ----------------
__device__ __forceinline__ void split1(float v, unsigned short& h, unsigned short& l) {
    uint32_t b = __float_as_uint(v);
    h = (unsigned short)(b >> 16);
    float r = v - __uint_as_float(b & 0xffff0000u);
    l = __bfloat16_as_ushort(__float2bfloat16(r));
}

__global__ void split_qk_kernel(const float4* __restrict__ Q, const float4* __restrict__ K,
                                unsigned short* __restrict__ qh, unsigned short* __restrict__ ql,
                                unsigned short* __restrict__ kh, unsigned short* __restrict__ kl,
                                int n4) {
    for (int i = blockIdx.x * blockDim.x + threadIdx.x; i < n4; i += gridDim.x * blockDim.x) {
        unsigned short h0,h1,h2,h3,l0,l1,l2,l3;
        float4 q = Q[i];
        split1(q.x,h0,l0); split1(q.y,h1,l1); split1(q.z,h2,l2); split1(q.w,h3,l3);
        *reinterpret_cast<uint2*>(qh + 4*(size_t)i) =
            make_uint2((uint32_t)h0 | ((uint32_t)h1<<16), (uint32_t)h2 | ((uint32_t)h3<<16));
        *reinterpret_cast<uint2*>(ql + 4*(size_t)i) =
            make_uint2((uint32_t)l0 | ((uint32_t)l1<<16), (uint32_t)l2 | ((uint32_t)l3<<16));
        float4 k = K[i];
        split1(k.x,h0,l0); split1(k.y,h1,l1); split1(k.z,h2,l2); split1(k.w,h3,l3);
        *reinterpret_cast<uint2*>(kh + 4*(size_t)i) =
            make_uint2((uint32_t)h0 | ((uint32_t)h1<<16), (uint32_t)h2 | ((uint32_t)h3<<16));
        *reinterpret_cast<uint2*>(kl + 4*(size_t)i) =
            make_uint2((uint32_t)l0 | ((uint32_t)l1<<16), (uint32_t)l2 | ((uint32_t)l3<<16));
    }
}

__global__ void v_transpose_split_kernel(const float* __restrict__ V,
                                         unsigned short* __restrict__ vh,
                                         unsigned short* __restrict__ vl) {
    __shared__ float t[32][33];
    int h = blockIdx.z, s0 = blockIdx.x * 32, d0 = blockIdx.y * 32;
    int tx = threadIdx.x, ty = threadIdx.y;
    const float* src = V + ((size_t)h * SEQ + s0) * DH + d0;
#pragma unroll
    for (int j = 0; j < 32; j += 8)
        t[ty + j][tx] = src[(size_t)(ty + j) * DH + tx];
    __syncthreads();
#pragma unroll
    for (int j = 0; j < 32; j += 8) {
        unsigned short hh, ll;
        split1(t[tx][ty + j], hh, ll);
        size_t o = ((size_t)h * DH + d0 + ty + j) * SEQ + s0 + tx;
        vh[o] = hh; vl[o] = ll;
    }
}

// ---------------- stage loader (cp.async, swizzled) ----------------
__device__ __forceinline__ void stage_load(uint32_t stg,
                                           const unsigned short* gkh, const unsigned short* gkl,
                                           const unsigned short* gvh, const unsigned short* gvl,
                                           int tid) {
#pragma unroll
    for (int t = 0; t < 4; ++t) {
        int idx = tid + t * NT;
        int r = idx >> 4, c16 = idx & 15;
        uint32_t d = stg + S_KH + ((uint32_t)r << 8) + (uint32_t)((c16 ^ (r & 7)) << 4);
        cp16(d, gkh + (size_t)r * DH + c16 * 8);
        cp16(d + (S_KL - S_KH), gkl + (size_t)r * DH + c16 * 8);
    }
#pragma unroll
    for (int t = 0; t < 4; ++t) {
        int idx = tid + t * NT;
        int r = idx >> 3, c16 = idx & 7;
        uint32_t d = stg + S_VH + ((uint32_t)r << 7) + (uint32_t)((c16 ^ (r & 7)) << 4);
        cp16(d, gvh + (size_t)r * SEQ + c16 * 8);
        cp16(d + (S_VL - S_VH), gvl + (size_t)r * SEQ + c16 * 8);
    }
}

// ---------------- main attention kernel ----------------
// 8 warps, pure M-partition: warp owns 16 query rows x full N. Q frags hoisted to regs.
__global__ __launch_bounds__(NT, 1)
void fa_hmma_kernel(float* __restrict__ Out) {
    extern __shared__ char smc[];
    const uint32_t sb = smem_u32(smc);
    const int tid  = threadIdx.x;
    const int lane = tid & 31;
    const int warp = tid >> 5;
    const int head = blockIdx.y;
    const int q0   = blockIdx.x * BM;
    const size_t base = (size_t)head * SEQ * DH;

    const unsigned short* gqh = g_qhi + base + (size_t)q0 * DH;
    const unsigned short* gql = g_qlo + base + (size_t)q0 * DH;
    const unsigned short* gkh0 = g_khi + base;
    const unsigned short* gkl0 = g_klo + base;
    const unsigned short* gvh0 = g_vhi + (size_t)head * DH * SEQ;
    const unsigned short* gvl0 = g_vlo + (size_t)head * DH * SEQ;

    // prefetch stages 0, 1 (K/V)
    stage_load(sb + 0u,      gkh0,          gkl0,          gvh0,      gvl0,      tid);
    CP_COMMIT();
    stage_load(sb + STG_SZ,  gkh0 + BN*DH,  gkl0 + BN*DH,  gvh0 + BN, gvl0 + BN, tid);
    CP_COMMIT();

    // stage Q (hi/lo) into buffer 2 (plain LDG/STS), then hoist fragments to regs
    {
        char* q2 = smc + 2u * STG_SZ;
        for (int idx = tid; idx < 2048; idx += NT) {
            int r = idx >> 4, c16 = idx & 15;
            uint32_t d = ((uint32_t)r << 8) + (uint32_t)((c16 ^ (r & 7)) << 4);
            *reinterpret_cast<uint4*>(q2 + d) =
                *reinterpret_cast<const uint4*>(gqh + (size_t)r * DH + c16 * 8);
            *reinterpret_cast<uint4*>(q2 + 32768u + d) =
                *reinterpret_cast<const uint4*>(gql + (size_t)r * DH + c16 * 8);
        }
    }
    __syncthreads();

    // ldmatrix lane geometry
    const int r0    = warp * 16;
    const int a_row = r0 + (lane & 7) + ((lane >> 3) & 1) * 8;
    const int a_c8  = lane >> 4;
    const int axr   = a_row & 7;
    const int b_row = (lane & 7) + ((lane >> 4) << 3);
    const int b_c8  = (lane >> 3) & 1;
    const int bxr   = b_row & 7;

    uint32_t qfh[8][4], qfl[8][4];
#pragma unroll
    for (int ks = 0; ks < 8; ++ks) {
        uint32_t aaddr = sb + 2u * STG_SZ + (uint32_t)(a_row << 8) +
                         (uint32_t)(((2 * ks + a_c8) ^ axr) << 4);
        LDSM4(qfh[ks], aaddr);
        LDSM4(qfl[ks], aaddr + 32768u);
    }
    __syncthreads();   // all warps own Q frags; buffer 2 is now free for the ring

    float co[16][4];
#pragma unroll
    for (int i = 0; i < 16; ++i)
#pragma unroll
        for (int j = 0; j < 4; ++j) co[i][j] = 0.0f;
    float lsum0 = 0.0f, lsum1 = 0.0f;

    uint32_t stg    = sb;                    // buffer for iter i   (i%3)
    uint32_t stg_pf = sb + 2u * STG_SZ;      // buffer for iter i+2 ((i+2)%3)

    for (int i = 0; i < NIT; ++i) {
        if (i == NIT - 1) { CP_WAIT_0(); } else { CP_WAIT_1(); }
        __syncthreads();   // publish stage i; retire stage i-1 (== prefetch target)

        if (i + 2 < NIT) {
            const int key0 = (i + 2) * BN;
            stage_load(stg_pf, gkh0 + (size_t)key0 * DH, gkl0 + (size_t)key0 * DH,
                       gvh0 + key0, gvl0 + key0, tid);
            CP_COMMIT();
        }

        // ---- S = Q K^T (3-product hi/lo), Q from registers ----
        float cs[8][4];
#pragma unroll
        for (int t = 0; t < 8; ++t)
#pragma unroll
            for (int j = 0; j < 4; ++j) cs[t][j] = 0.0f;

#pragma unroll
        for (int ks = 0; ks < 8; ++ks) {
#pragma unroll
            for (int n2 = 0; n2 < 4; ++n2) {
                uint32_t kh[4], kl[4];
                uint32_t baddr = stg + S_KH + (uint32_t)((n2 * 16 + b_row) << 8) +
                                 (uint32_t)(((2 * ks + b_c8) ^ bxr) << 4);
                LDSM4(kh, baddr);
                LDSM4(kl, baddr + (S_KL - S_KH));
                MMA(cs[2 * n2],     qfh[ks], kh[0], kh[1]);
                MMA(cs[2 * n2 + 1], qfh[ks], kh[2], kh[3]);
                MMA(cs[2 * n2],     qfh[ks], kl[0], kl[1]);
                MMA(cs[2 * n2 + 1], qfh[ks], kl[2], kl[3]);
                MMA(cs[2 * n2],     qfl[ks], kh[0], kh[1]);
                MMA(cs[2 * n2 + 1], qfl[ks], kh[2], kh[3]);
            }
        }

        // ---- softmax (no max: logits bounded ~65 < fp32 exp range) ----
        uint32_t ph[4][4], pl[4][4];
#pragma unroll
        for (int j = 0; j < 4; ++j) {
            float e0 = __expf(cs[2*j][0]),   e1 = __expf(cs[2*j][1]);
            float e2 = __expf(cs[2*j][2]),   e3 = __expf(cs[2*j][3]);
            float e4 = __expf(cs[2*j+1][0]), e5 = __expf(cs[2*j+1][1]);
            float e6 = __expf(cs[2*j+1][2]), e7 = __expf(cs[2*j+1][3]);
            lsum0 += (e0 + e1) + (e4 + e5);
            lsum1 += (e2 + e3) + (e6 + e7);
            uint32_t u0 = __float_as_uint(e0), u1 = __float_as_uint(e1);
            uint32_t u2 = __float_as_uint(e2), u3 = __float_as_uint(e3);
            uint32_t u4 = __float_as_uint(e4), u5 = __float_as_uint(e5);
            uint32_t u6 = __float_as_uint(e6), u7 = __float_as_uint(e7);
            ph[j][0] = __byte_perm(u0, u1, 0x7632);
            ph[j][1] = __byte_perm(u2, u3, 0x7632);
            ph[j][2] = __byte_perm(u4, u5, 0x7632);
            ph[j][3] = __byte_perm(u6, u7, 0x7632);
            pl[j][0] = pack_lo_bf16x2(e0 - __uint_as_float(u0 & 0xffff0000u),
                                      e1 - __uint_as_float(u1 & 0xffff0000u));
            pl[j][1] = pack_lo_bf16x2(e2 - __uint_as_float(u2 & 0xffff0000u),
                                      e3 - __uint_as_float(u3 & 0xffff0000u));
            pl[j][2] = pack_lo_bf16x2(e4 - __uint_as_float(u4 & 0xffff0000u),
                                      e5 - __uint_as_float(u5 & 0xffff0000u));
            pl[j][3] = pack_lo_bf16x2(e6 - __uint_as_float(u6 & 0xffff0000u),
                                      e7 - __uint_as_float(u7 & 0xffff0000u));
        }

        // ---- O += P V (3-product hi/lo), V^T tiles from smem ----
#pragma unroll
        for (int j = 0; j < 4; ++j) {
#pragma unroll
            for (int n2 = 0; n2 < 8; ++n2) {
                uint32_t vh[4], vl[4];
                uint32_t vaddr = stg + S_VH + (uint32_t)((n2 * 16 + b_row) << 7) +
                                 (uint32_t)(((2 * j + b_c8) ^ bxr) << 4);
                LDSM4(vh, vaddr);
                LDSM4(vl, vaddr + (S_VL - S_VH));
                MMA(co[2 * n2],     ph[j], vh[0], vh[1]);
                MMA(co[2 * n2 + 1], ph[j], vh[2], vh[3]);
                MMA(co[2 * n2],     pl[j], vh[0], vh[1]);
                MMA(co[2 * n2 + 1], pl[j], vh[2], vh[3]);
                MMA(co[2 * n2],     ph[j], vl[0], vl[1]);
                MMA(co[2 * n2 + 1], ph[j], vl[2], vl[3]);
            }
        }

        // rotate ring pointers: next iter's buffer, next prefetch target
        uint32_t next = stg + STG_SZ;
        if (next >= sb + 3u * STG_SZ) next = sb;
        uint32_t nextpf = stg_pf + STG_SZ;
        if (nextpf >= sb + 3u * STG_SZ) nextpf = sb;
        stg = next;
        stg_pf = nextpf;
    }

    // ---- epilogue: reduce l within quads, divide, store ----
    lsum0 += __shfl_xor_sync(0xffffffffu, lsum0, 1);
    lsum0 += __shfl_xor_sync(0xffffffffu, lsum0, 2);
    lsum1 += __shfl_xor_sync(0xffffffffu, lsum1, 1);
    lsum1 += __shfl_xor_sync(0xffffffffu, lsum1, 2);
    float inv0 = 1.0f / lsum0;
    float inv1 = 1.0f / lsum1;

    float* o0 = Out + base + (size_t)(q0 + r0 + (lane >> 2)) * DH;
    float* o1 = o0 + 8 * DH;
    const int cb = (lane & 3) * 2;
#pragma unroll
    for (int nt = 0; nt < 16; ++nt) {
        int c = nt * 8 + cb;
        float2 w0 = make_float2(co[nt][0] * inv0, co[nt][1] * inv0);
        float2 w1 = make_float2(co[nt][2] * inv1, co[nt][3] * inv1);
        *reinterpret_cast<float2*>(o0 + c) = w0;
        *reinterpret_cast<float2*>(o1 + c) = w1;
    }
}

extern "C" void kernel_launch(void* const* d_in, const int* in_sizes, int n_in,
                              void* d_out, int out_size) {
    const float* Q = (const float*)d_in[0];
    const float* K = (const float*)d_in[1];
    const float* V = (const float*)d_in[2];
    float* O = (float*)d_out;

    unsigned short *qh, *ql, *kh, *kl, *vh, *vl;
    cudaGetSymbolAddress((void**)&qh, g_qhi);
    cudaGetSymbolAddress((void**)&ql, g_qlo);
    cudaGetSymbolAddress((void**)&kh, g_khi);
    cudaGetSymbolAddress((void**)&kl, g_klo);
    cudaGetSymbolAddress((void**)&vh, g_vhi);
    cudaGetSymbolAddress((void**)&vl, g_vlo);

    split_qk_kernel<<<1024, 256>>>((const float4*)Q, (const float4*)K,
                                   qh, ql, kh, kl, NELEM / 4);
    v_transpose_split_kernel<<<dim3(SEQ / 32, DH / 32, HEADS), dim3(32, 8)>>>(V, vh, vl);

    cudaFuncSetAttribute(fa_hmma_kernel,
                         cudaFuncAttributeMaxDynamicSharedMemorySize, SMEM_MAIN);
    dim3 grid(SEQ / BM, HEADS);
    fa_hmma_kernel<<<grid, NT, SMEM_MAIN>>>(O);
}

// round 7
// speedup vs baseline: 1.3976x; 1.3268x over previous
#include <cuda_runtime.h>
#include <cuda_bf16.h>
#include <cuda_fp16.h>
#include <cstdint>

#define HEADS 32
#define SEQ   2048
#define DH    128
#define BM    128
#define BN    64
#define NIT   (SEQ / BN)
#define NT    256
#define NELEM (HEADS * SEQ * DH)

// scratch (device globals: sanctioned scratch, no allocs)
__device__ __align__(16) unsigned short g_qhi[NELEM];
__device__ __align__(16) unsigned short g_qlo[NELEM];
__device__ __align__(16) unsigned short g_khi[NELEM];
__device__ __align__(16) unsigned short g_klo[NELEM];
__device__ __align__(16) unsigned short g_vf[NELEM];   // V^T [head][d][s], fp16

// 3-stage smem ring; stage: KH 16K, KL 16K, V 16K
#define STG_SZ  49152u
#define S_KH    0u
#define S_KL    16384u
#define S_V     32768u
#define SMEM_MAIN (3u * STG_SZ)   // 144KB

// ---------------- PTX helpers ----------------
__device__ __forceinline__ uint32_t smem_u32(const void* p) {
    uint32_t a;
    asm("{ .reg .u64 t; cvta.to.shared.u64 t, %1; cvt.u32.u64 %0, t; }" : "=r"(a) : "l"(p));
    return a;
}
__device__ __forceinline__ void cp16(uint32_t dst, const void* src) {
    asm volatile("cp.async.cg.shared.global [%0], [%1], 16;" :: "r"(dst), "l"(src) : "memory");
}
#define CP_COMMIT() asm volatile("cp.async.commit_group;" ::: "memory")
#define CP_WAIT_1() asm volatile("cp.async.wait_group 1;" ::: "memory")
#define CP_WAIT_0() asm volatile("cp.async.wait_group 0;" ::: "memory")

#define LDSM4(r, a) \
    asm volatile("ldmatrix.sync.aligned.m8n8.x4.shared.b16 {%0,%1,%2,%3}, [%4];" \
        : "=r"((r)[0]), "=r"((r)[1]), "=r"((r)[2]), "=r"((r)[3]) : "r"(a))

#define MMAB(c, a, b0, b1) \
    asm volatile("mma.sync.aligned.m16n8k16.row.col.f32.bf16.bf16.f32 " \
        "{%0,%1,%2,%3}, {%4,%5,%6,%7}, {%8,%9}, {%0,%1,%2,%3};" \
        : "+f"((c)[0]), "+f"((c)[1]), "+f"((c)[2]), "+f"((c)[3]) \
        : "r"((a)[0]), "r"((a)[1]), "r"((a)[2]), "r"((a)[3]), "r"(b0), "r"(b1))

#define MMAH(c, a, b0, b1) \
    asm volatile("mma.sync.aligned.m16n8k16.row.col.f32.f16.f16.f32 " \
        "{%0,%1,%2,%3}, {%4,%5,%6,%7}, {%8,%9}, {%0,%1,%2,%3};" \
        : "+f"((c)[0]), "+f"((c)[1]), "+f"((c)[2]), "+f"((c)[3]) \
        : "r"((a)[0]), "r"((a)[1]), "r"((a)[2]), "r"((a)[3]), "r"(b0), "r"(b1))

// pack two fp32 to f16x2: lo half = x, hi half = y
__device__ __forceinline__ uint32_t pack_f16x2(float x, float y) {
    uint32_t d;
    asm("cvt.rn.f16x2.f32 %0, %1, %2;" : "=r"(d) : "f"(y), "f"(x));
    return d;
}

// ---------------- hi/lo split ----------------
__device__ __forceinline__ void split1(float v, unsigned short& h, unsigned short& l) {
    uint32_t b = __float_as_uint(v);
    h = (unsigned short)(b >> 16);
    float r = v - __uint_as_float(b & 0xffff0000u);
    l = __bfloat16_as_ushort(__float2bfloat16(r));
}

__global__ void split_qk_kernel(const float4* __restrict__ Q, const float4* __restrict__ K,
                                unsigned short* __restrict__ qh, unsigned short* __restrict__ ql,
                                unsigned short* __restrict__ kh, unsigned short* __restrict__ kl,
                                int n4) {
    for (int i = blockIdx.x * blockDim.x + threadIdx.x; i < n4; i += gridDim.x * blockDim.x) {
        unsigned short h0,h1,h2,h3,l0,l1,l2,l3;
        float4 q = Q[i];
        split1(q.x,h0,l0); split1(q.y,h1,l1); split1(q.z,h2,l2); split1(q.w,h3,l3);
        *reinterpret_cast<uint2*>(qh + 4*(size_t)i) =
            make_uint2((uint32_t)h0 | ((uint32_t)h1<<16), (uint32_t)h2 | ((uint32_t)h3<<16));
        *reinterpret_cast<uint2*>(ql + 4*(size_t)i) =
            make_uint2((uint32_t)l0 | ((uint32_t)l1<<16), (uint32_t)l2 | ((uint32_t)l3<<16));
        float4 k = K[i];
        split1(k.x,h0,l0); split1(k.y,h1,l1); split1(k.z,h2,l2); split1(k.w,h3,l3);
        *reinterpret_cast<uint2*>(kh + 4*(size_t)i) =
            make_uint2((uint32_t)h0 | ((uint32_t)h1<<16), (uint32_t)h2 | ((uint32_t)h3<<16));
        *reinterpret_cast<uint2*>(kl + 4*(size_t)i) =
            make_uint2((uint32_t)l0 | ((uint32_t)l1<<16), (uint32_t)l2 | ((uint32_t)l3<<16));
    }
}

__global__ void v_transpose_kernel(const float* __restrict__ V,
                                   unsigned short* __restrict__ vf) {
    __shared__ float t[32][33];
    int h = blockIdx.z, s0 = blockIdx.x * 32, d0 = blockIdx.y * 32;
    int tx = threadIdx.x, ty = threadIdx.y;
    const float* src = V + ((size_t)h * SEQ + s0) * DH + d0;
#pragma unroll
    for (int j = 0; j < 32; j += 8)
        t[ty + j][tx] = src[(size_t)(ty + j) * DH + tx];
    __syncthreads();
#pragma unroll
    for (int j = 0; j < 32; j += 8) {
        __half hv = __float2half_rn(t[tx][ty + j]);
        size_t o = ((size_t)h * DH + d0 + ty + j) * SEQ + s0 + tx;
        vf[o] = *reinterpret_cast<unsigned short*>(&hv);
    }
}

// ---------------- stage loader (cp.async, swizzled) ----------------
__device__ __forceinline__ void stage_load(uint32_t stg,
                                           const unsigned short* gkh, const unsigned short* gkl,
                                           const unsigned short* gv, int tid) {
#pragma unroll
    for (int t = 0; t < 4; ++t) {
        int idx = tid + t * NT;
        int r = idx >> 4, c16 = idx & 15;
        uint32_t d = stg + S_KH + ((uint32_t)r << 8) + (uint32_t)((c16 ^ (r & 7)) << 4);
        cp16(d, gkh + (size_t)r * DH + c16 * 8);
        cp16(d + (S_KL - S_KH), gkl + (size_t)r * DH + c16 * 8);
    }
#pragma unroll
    for (int t = 0; t < 4; ++t) {
        int idx = tid + t * NT;
        int r = idx >> 3, c16 = idx & 7;
        uint32_t d = stg + S_V + ((uint32_t)r << 7) + (uint32_t)((c16 ^ (r & 7)) << 4);
        cp16(d, gv + (size_t)r * SEQ + c16 * 8);
    }
}

// ---------------- main attention kernel ----------------
// 8 warps, pure M-partition (16 query rows x full N per warp).
// Online softmax: running max m0/m1, fp16 P, fp16 V, single-product PV.
__global__ __launch_bounds__(NT, 1)
void fa_hmma_kernel(float* __restrict__ Out) {
    extern __shared__ char smc[];
    const uint32_t sb = smem_u32(smc);
    const int tid  = threadIdx.x;
    const int lane = tid & 31;
    const int warp = tid >> 5;
    const int head = blockIdx.y;
    const int q0   = blockIdx.x * BM;
    const size_t base = (size_t)head * SEQ * DH;

    const unsigned short* gqh = g_qhi + base + (size_t)q0 * DH;
    const unsigned short* gql = g_qlo + base + (size_t)q0 * DH;
    const unsigned short* gkh0 = g_khi + base;
    const unsigned short* gkl0 = g_klo + base;
    const unsigned short* gv0  = g_vf + (size_t)head * DH * SEQ;

    // ---- load Q hi/lo into smem [0,64K), hoist fragments, then start ring ----
    for (int idx = tid; idx < 2048; idx += NT) {
        int r = idx >> 4, c16 = idx & 15;
        uint32_t d = ((uint32_t)r << 8) + (uint32_t)((c16 ^ (r & 7)) << 4);
        *reinterpret_cast<uint4*>(smc + d) =
            *reinterpret_cast<const uint4*>(gqh + (size_t)r * DH + c16 * 8);
        *reinterpret_cast<uint4*>(smc + 32768u + d) =
            *reinterpret_cast<const uint4*>(gql + (size_t)r * DH + c16 * 8);
    }
    __syncthreads();

    // ldmatrix lane geometry
    const int r0    = warp * 16;
    const int a_row = r0 + (lane & 7) + ((lane >> 3) & 1) * 8;
    const int a_c8  = lane >> 4;
    const int axr   = a_row & 7;
    const int b_row = (lane & 7) + ((lane >> 4) << 3);
    const int b_c8  = (lane >> 3) & 1;
    const int bxr   = b_row & 7;

    uint32_t qfh[8][4], qfl[8][4];
#pragma unroll
    for (int ks = 0; ks < 8; ++ks) {
        uint32_t aaddr = sb + (uint32_t)(a_row << 8) +
                         (uint32_t)(((2 * ks + a_c8) ^ axr) << 4);
        LDSM4(qfh[ks], aaddr);
        LDSM4(qfl[ks], aaddr + 32768u);
    }
    __syncthreads();   // Q frags in regs; smem free for the ring

    // prefetch stages 0, 1
    stage_load(sb + 0u,     gkh0,           gkl0,           gv0,      tid);
    CP_COMMIT();
    stage_load(sb + STG_SZ, gkh0 + BN * DH, gkl0 + BN * DH, gv0 + BN, tid);
    CP_COMMIT();

    float co[16][4];
#pragma unroll
    for (int i = 0; i < 16; ++i)
#pragma unroll
        for (int j = 0; j < 4; ++j) co[i][j] = 0.0f;
    float lsum0 = 0.0f, lsum1 = 0.0f;
    float m0 = -1e30f, m1 = -1e30f;

    uint32_t stg    = sb;                    // buffer for iter i
    uint32_t stg_pf = sb + 2u * STG_SZ;      // buffer for iter i+2

    for (int i = 0; i < NIT; ++i) {
        if (i == NIT - 1) { CP_WAIT_0(); } else { CP_WAIT_1(); }
        __syncthreads();

        if (i + 2 < NIT) {
            const int key0 = (i + 2) * BN;
            stage_load(stg_pf, gkh0 + (size_t)key0 * DH, gkl0 + (size_t)key0 * DH,
                       gv0 + key0, tid);
            CP_COMMIT();
        }

        // ---- S = Q K^T (bf16 3-product hi/lo), Q from registers ----
        float cs[8][4];
#pragma unroll
        for (int t = 0; t < 8; ++t)
#pragma unroll
            for (int j = 0; j < 4; ++j) cs[t][j] = 0.0f;

#pragma unroll
        for (int ks = 0; ks < 8; ++ks) {
#pragma unroll
            for (int n2 = 0; n2 < 4; ++n2) {
                uint32_t kh[4], kl[4];
                uint32_t baddr = stg + S_KH + (uint32_t)((n2 * 16 + b_row) << 8) +
                                 (uint32_t)(((2 * ks + b_c8) ^ bxr) << 4);
                LDSM4(kh, baddr);
                LDSM4(kl, baddr + (S_KL - S_KH));
                MMAB(cs[2 * n2],     qfh[ks], kh[0], kh[1]);
                MMAB(cs[2 * n2 + 1], qfh[ks], kh[2], kh[3]);
                MMAB(cs[2 * n2],     qfh[ks], kl[0], kl[1]);
                MMAB(cs[2 * n2 + 1], qfh[ks], kl[2], kl[3]);
                MMAB(cs[2 * n2],     qfl[ks], kh[0], kh[1]);
                MMAB(cs[2 * n2 + 1], qfl[ks], kh[2], kh[3]);
            }
        }

        // ---- online softmax: tile max -> rescale -> exp -> fp16 pack ----
        float tA = cs[0][0], tB = cs[0][2];
#pragma unroll
        for (int t = 0; t < 8; ++t) {
            tA = fmaxf(tA, fmaxf(cs[t][0], cs[t][1]));
            tB = fmaxf(tB, fmaxf(cs[t][2], cs[t][3]));
        }
        tA = fmaxf(tA, __shfl_xor_sync(0xffffffffu, tA, 1));
        tA = fmaxf(tA, __shfl_xor_sync(0xffffffffu, tA, 2));
        tB = fmaxf(tB, __shfl_xor_sync(0xffffffffu, tB, 1));
        tB = fmaxf(tB, __shfl_xor_sync(0xffffffffu, tB, 2));
        float mnA = fmaxf(m0, tA), mnB = fmaxf(m1, tB);
        float scA = __expf(m0 - mnA), scB = __expf(m1 - mnB);
        m0 = mnA; m1 = mnB;
        lsum0 *= scA; lsum1 *= scB;
#pragma unroll
        for (int nt = 0; nt < 16; ++nt) {
            co[nt][0] *= scA; co[nt][1] *= scA;
            co[nt][2] *= scB; co[nt][3] *= scB;
        }

        uint32_t pf[4][4];
#pragma unroll
        for (int j = 0; j < 4; ++j) {
            float e0 = __expf(cs[2*j][0]   - mnA), e1 = __expf(cs[2*j][1]   - mnA);
            float e2 = __expf(cs[2*j][2]   - mnB), e3 = __expf(cs[2*j][3]   - mnB);
            float e4 = __expf(cs[2*j+1][0] - mnA), e5 = __expf(cs[2*j+1][1] - mnA);
            float e6 = __expf(cs[2*j+1][2] - mnB), e7 = __expf(cs[2*j+1][3] - mnB);
            lsum0 += (e0 + e1) + (e4 + e5);
            lsum1 += (e2 + e3) + (e6 + e7);
            pf[j][0] = pack_f16x2(e0, e1);
            pf[j][1] = pack_f16x2(e2, e3);
            pf[j][2] = pack_f16x2(e4, e5);
            pf[j][3] = pack_f16x2(e6, e7);
        }

        // ---- O += P V (single fp16 product) ----
#pragma unroll
        for (int j = 0; j < 4; ++j) {
#pragma unroll
            for (int n2 = 0; n2 < 8; ++n2) {
                uint32_t vf[4];
                uint32_t vaddr = stg + S_V + (uint32_t)((n2 * 16 + b_row) << 7) +
                                 (uint32_t)(((2 * j + b_c8) ^ bxr) << 4);
                LDSM4(vf, vaddr);
                MMAH(co[2 * n2],     pf[j], vf[0], vf[1]);
                MMAH(co[2 * n2 + 1], pf[j], vf[2], vf[3]);
            }
        }

        // rotate ring
        uint32_t next = stg + STG_SZ;
        if (next >= sb + 3u * STG_SZ) next = sb;
        uint32_t nextpf = stg_pf + STG_SZ;
        if (nextpf >= sb + 3u * STG_SZ) nextpf = sb;
        stg = next;
        stg_pf = nextpf;
    }

    // ---- epilogue: reduce l within quads, divide, store ----
    lsum0 += __shfl_xor_sync(0xffffffffu, lsum0, 1);
    lsum0 += __shfl_xor_sync(0xffffffffu, lsum0, 2);
    lsum1 += __shfl_xor_sync(0xffffffffu, lsum1, 1);
    lsum1 += __shfl_xor_sync(0xffffffffu, lsum1, 2);
    float inv0 = 1.0f / lsum0;
    float inv1 = 1.0f / lsum1;

    float* o0 = Out + base + (size_t)(q0 + r0 + (lane >> 2)) * DH;
    float* o1 = o0 + 8 * DH;
    const int cb = (lane & 3) * 2;
#pragma unroll
    for (int nt = 0; nt < 16; ++nt) {
        int c = nt * 8 + cb;
        float2 w0 = make_float2(co[nt][0] * inv0, co[nt][1] * inv0);
        float2 w1 = make_float2(co[nt][2] * inv1, co[nt][3] * inv1);
        *reinterpret_cast<float2*>(o0 + c) = w0;
        *reinterpret_cast<float2*>(o1 + c) = w1;
    }
}

extern "C" void kernel_launch(void* const* d_in, const int* in_sizes, int n_in,
                              void* d_out, int out_size) {
    const float* Q = (const float*)d_in[0];
    const float* K = (const float*)d_in[1];
    const float* V = (const float*)d_in[2];
    float* O = (float*)d_out;

    unsigned short *qh, *ql, *kh, *kl, *vf;
    cudaGetSymbolAddress((void**)&qh, g_qhi);
    cudaGetSymbolAddress((void**)&ql, g_qlo);
    cudaGetSymbolAddress((void**)&kh, g_khi);
    cudaGetSymbolAddress((void**)&kl, g_klo);
    cudaGetSymbolAddress((void**)&vf, g_vf);

    split_qk_kernel<<<1024, 256>>>((const float4*)Q, (const float4*)K,
                                   qh, ql, kh, kl, NELEM / 4);
    v_transpose_kernel<<<dim3(SEQ / 32, DH / 32, HEADS), dim3(32, 8)>>>(V, vf);

    cudaFuncSetAttribute(fa_hmma_kernel,
                         cudaFuncAttributeMaxDynamicSharedMemorySize, SMEM_MAIN);
    dim3 grid(SEQ / BM, HEADS);
    fa_hmma_kernel<<<grid, NT, SMEM_MAIN>>>(O);
}

// round 8
// speedup vs baseline: 1.4038x; 1.0044x over previous
#include <cuda_runtime.h>
#include <cuda_bf16.h>
#include <cuda_fp16.h>
#include <cstdint>

#define HEADS 32
#define SEQ   2048
#define DH    128
#define BM    128
#define BN    64
#define NIT   (SEQ / BN)
#define NT    256
#define NELEM (HEADS * SEQ * DH)

// scratch (device globals: sanctioned scratch, no allocs)
__device__ __align__(16) unsigned short g_qhi[NELEM];   // Q*log2(e), bf16 hi
__device__ __align__(16) unsigned short g_qlo[NELEM];   // residual, bf16
__device__ __align__(16) unsigned short g_khi[NELEM];
__device__ __align__(16) unsigned short g_klo[NELEM];
__device__ __align__(16) unsigned short g_vf[NELEM];    // V^T [head][d][s], fp16

// 3-stage smem ring; stage: KH 16K, KL 16K, V 16K
#define STG_SZ  49152u
#define S_KH    0u
#define S_KL    16384u
#define S_V     32768u
#define SMEM_MAIN (3u * STG_SZ)   // 144KB

// ---------------- PTX helpers ----------------
__device__ __forceinline__ uint32_t smem_u32(const void* p) {
    uint32_t a;
    asm("{ .reg .u64 t; cvta.to.shared.u64 t, %1; cvt.u32.u64 %0, t; }" : "=r"(a) : "l"(p));
    return a;
}
__device__ __forceinline__ void cp16(uint32_t dst, const void* src) {
    asm volatile("cp.async.cg.shared.global [%0], [%1], 16;" :: "r"(dst), "l"(src) : "memory");
}
#define CP_COMMIT() asm volatile("cp.async.commit_group;" ::: "memory")
#define CP_WAIT_1() asm volatile("cp.async.wait_group 1;" ::: "memory")
#define CP_WAIT_0() asm volatile("cp.async.wait_group 0;" ::: "memory")

#define LDSM4(r, a) \
    asm volatile("ldmatrix.sync.aligned.m8n8.x4.shared.b16 {%0,%1,%2,%3}, [%4];" \
        : "=r"((r)[0]), "=r"((r)[1]), "=r"((r)[2]), "=r"((r)[3]) : "r"(a))

#define MMAB(c, a, b0, b1) \
    asm volatile("mma.sync.aligned.m16n8k16.row.col.f32.bf16.bf16.f32 " \
        "{%0,%1,%2,%3}, {%4,%5,%6,%7}, {%8,%9}, {%0,%1,%2,%3};" \
        : "+f"((c)[0]), "+f"((c)[1]), "+f"((c)[2]), "+f"((c)[3]) \
        : "r"((a)[0]), "r"((a)[1]), "r"((a)[2]), "r"((a)[3]), "r"(b0), "r"(b1))

#define MMAH(c, a, b0, b1) \
    asm volatile("mma.sync.aligned.m16n8k16.row.col.f32.f16.f16.f32 " \
        "{%0,%1,%2,%3}, {%4,%5,%6,%7}, {%8,%9}, {%0,%1,%2,%3};" \
        : "+f"((c)[0]), "+f"((c)[1]), "+f"((c)[2]), "+f"((c)[3]) \
        : "r"((a)[0]), "r"((a)[1]), "r"((a)[2]), "r"((a)[3]), "r"(b0), "r"(b1))

__device__ __forceinline__ uint32_t pack_f16x2(float x, float y) {
    uint32_t d;
    asm("cvt.rn.f16x2.f32 %0, %1, %2;" : "=r"(d) : "f"(y), "f"(x));
    return d;
}
__device__ __forceinline__ float ex2(float x) {
    float r;
    asm("ex2.approx.f32 %0, %1;" : "=f"(r) : "f"(x));
    return r;
}

// ---------------- hi/lo split ----------------
__device__ __forceinline__ void split1(float v, unsigned short& h, unsigned short& l) {
    uint32_t b = __float_as_uint(v);
    h = (unsigned short)(b >> 16);
    float r = v - __uint_as_float(b & 0xffff0000u);
    l = __bfloat16_as_ushort(__float2bfloat16(r));
}

#define LOG2E 1.44269504088896340736f

__global__ void split_qk_kernel(const float4* __restrict__ Q, const float4* __restrict__ K,
                                unsigned short* __restrict__ qh, unsigned short* __restrict__ ql,
                                unsigned short* __restrict__ kh, unsigned short* __restrict__ kl,
                                int n4) {
    for (int i = blockIdx.x * blockDim.x + threadIdx.x; i < n4; i += gridDim.x * blockDim.x) {
        unsigned short h0,h1,h2,h3,l0,l1,l2,l3;
        float4 q = Q[i];
        split1(q.x * LOG2E, h0, l0); split1(q.y * LOG2E, h1, l1);
        split1(q.z * LOG2E, h2, l2); split1(q.w * LOG2E, h3, l3);
        *reinterpret_cast<uint2*>(qh + 4*(size_t)i) =
            make_uint2((uint32_t)h0 | ((uint32_t)h1<<16), (uint32_t)h2 | ((uint32_t)h3<<16));
        *reinterpret_cast<uint2*>(ql + 4*(size_t)i) =
            make_uint2((uint32_t)l0 | ((uint32_t)l1<<16), (uint32_t)l2 | ((uint32_t)l3<<16));
        float4 k = K[i];
        split1(k.x,h0,l0); split1(k.y,h1,l1); split1(k.z,h2,l2); split1(k.w,h3,l3);
        *reinterpret_cast<uint2*>(kh + 4*(size_t)i) =
            make_uint2((uint32_t)h0 | ((uint32_t)h1<<16), (uint32_t)h2 | ((uint32_t)h3<<16));
        *reinterpret_cast<uint2*>(kl + 4*(size_t)i) =
            make_uint2((uint32_t)l0 | ((uint32_t)l1<<16), (uint32_t)l2 | ((uint32_t)l3<<16));
    }
}

__global__ void v_transpose_kernel(const float* __restrict__ V,
                                   unsigned short* __restrict__ vf) {
    __shared__ float t[32][33];
    int h = blockIdx.z, s0 = blockIdx.x * 32, d0 = blockIdx.y * 32;
    int tx = threadIdx.x, ty = threadIdx.y;
    const float* src = V + ((size_t)h * SEQ + s0) * DH + d0;
#pragma unroll
    for (int j = 0; j < 32; j += 8)
        t[ty + j][tx] = src[(size_t)(ty + j) * DH + tx];
    __syncthreads();
#pragma unroll
    for (int j = 0; j < 32; j += 8) {
        __half hv = __float2half_rn(t[tx][ty + j]);
        size_t o = ((size_t)h * DH + d0 + ty + j) * SEQ + s0 + tx;
        vf[o] = *reinterpret_cast<unsigned short*>(&hv);
    }
}

// ---------------- stage loader (cp.async, swizzled) ----------------
__device__ __forceinline__ void stage_load(uint32_t stg,
                                           const unsigned short* gkh, const unsigned short* gkl,
                                           const unsigned short* gv, int tid) {
#pragma unroll
    for (int t = 0; t < 4; ++t) {
        int idx = tid + t * NT;
        int r = idx >> 4, c16 = idx & 15;
        uint32_t d = stg + S_KH + ((uint32_t)r << 8) + (uint32_t)((c16 ^ (r & 7)) << 4);
        cp16(d, gkh + (size_t)r * DH + c16 * 8);
        cp16(d + (S_KL - S_KH), gkl + (size_t)r * DH + c16 * 8);
    }
#pragma unroll
    for (int t = 0; t < 4; ++t) {
        int idx = tid + t * NT;
        int r = idx >> 3, c16 = idx & 7;
        uint32_t d = stg + S_V + ((uint32_t)r << 7) + (uint32_t)((c16 ^ (r & 7)) << 4);
        cp16(d, gv + (size_t)r * SEQ + c16 * 8);
    }
}

// ---------------- main attention kernel ----------------
__global__ __launch_bounds__(NT, 1)
void fa_hmma_kernel(float* __restrict__ Out) {
    extern __shared__ char smc[];
    const uint32_t sb = smem_u32(smc);
    const int tid  = threadIdx.x;
    const int lane = tid & 31;
    const int warp = tid >> 5;
    const int head = blockIdx.y;
    const int q0   = blockIdx.x * BM;
    const size_t base = (size_t)head * SEQ * DH;

    const unsigned short* gqh = g_qhi + base + (size_t)q0 * DH;
    const unsigned short* gql = g_qlo + base + (size_t)q0 * DH;
    const unsigned short* gkh0 = g_khi + base;
    const unsigned short* gkl0 = g_klo + base;
    const unsigned short* gv0  = g_vf + (size_t)head * DH * SEQ;

    // ---- load Q hi/lo into smem, hoist fragments, then start ring ----
    for (int idx = tid; idx < 2048; idx += NT) {
        int r = idx >> 4, c16 = idx & 15;
        uint32_t d = ((uint32_t)r << 8) + (uint32_t)((c16 ^ (r & 7)) << 4);
        *reinterpret_cast<uint4*>(smc + d) =
            *reinterpret_cast<const uint4*>(gqh + (size_t)r * DH + c16 * 8);
        *reinterpret_cast<uint4*>(smc + 32768u + d) =
            *reinterpret_cast<const uint4*>(gql + (size_t)r * DH + c16 * 8);
    }
    __syncthreads();

    const int r0    = warp * 16;
    const int a_row = r0 + (lane & 7) + ((lane >> 3) & 1) * 8;
    const int a_c8  = lane >> 4;
    const int axr   = a_row & 7;
    const int b_row = (lane & 7) + ((lane >> 4) << 3);
    const int b_c8  = (lane >> 3) & 1;
    const int bxr   = b_row & 7;

    uint32_t qfh[8][4], qfl[8][4];
#pragma unroll
    for (int ks = 0; ks < 8; ++ks) {
        uint32_t aaddr = sb + (uint32_t)(a_row << 8) +
                         (uint32_t)(((2 * ks + a_c8) ^ axr) << 4);
        LDSM4(qfh[ks], aaddr);
        LDSM4(qfl[ks], aaddr + 32768u);
    }
    __syncthreads();   // Q frags in regs; smem free for the ring

    stage_load(sb + 0u,     gkh0,           gkl0,           gv0,      tid);
    CP_COMMIT();
    stage_load(sb + STG_SZ, gkh0 + BN * DH, gkl0 + BN * DH, gv0 + BN, tid);
    CP_COMMIT();

    float co[16][4];
#pragma unroll
    for (int i = 0; i < 16; ++i)
#pragma unroll
        for (int j = 0; j < 4; ++j) co[i][j] = 0.0f;
    float lsum0 = 0.0f, lsum1 = 0.0f;
    float m0 = -1e30f, m1 = -1e30f;

    uint32_t stg    = sb;
    uint32_t stg_pf = sb + 2u * STG_SZ;

    for (int i = 0; i < NIT; ++i) {
        if (i == NIT - 1) { CP_WAIT_0(); } else { CP_WAIT_1(); }
        __syncthreads();

        if (i + 2 < NIT) {
            const int key0 = (i + 2) * BN;
            stage_load(stg_pf, gkh0 + (size_t)key0 * DH, gkl0 + (size_t)key0 * DH,
                       gv0 + key0, tid);
            CP_COMMIT();
        }

        // ---- S = Q K^T (bf16 3-product hi/lo), K frags double-buffered ----
        float cs[8][4];
#pragma unroll
        for (int t = 0; t < 8; ++t)
#pragma unroll
            for (int j = 0; j < 4; ++j) cs[t][j] = 0.0f;

        uint32_t khA[4], klA[4], khB[4], klB[4];
        {
            uint32_t b0 = stg + S_KH + (uint32_t)(b_row << 8) +
                          (uint32_t)((b_c8 ^ bxr) << 4);
            LDSM4(khA, b0);
            LDSM4(klA, b0 + (S_KL - S_KH));
        }
#pragma unroll
        for (int t = 0; t < 32; ++t) {
            const int ks = t >> 2, n2 = t & 3;
            uint32_t* kh = (t & 1) ? khB : khA;
            uint32_t* kl = (t & 1) ? klB : klA;
            if (t < 31) {
                const int tn = t + 1;
                const int ksn = tn >> 2, n2n = tn & 3;
                uint32_t* khn = (tn & 1) ? khB : khA;
                uint32_t* kln = (tn & 1) ? klB : klA;
                uint32_t baddr = stg + S_KH +
                                 (uint32_t)((n2n * 16 + b_row) << 8) +
                                 (uint32_t)(((2 * ksn + b_c8) ^ bxr) << 4);
                LDSM4(khn, baddr);
                LDSM4(kln, baddr + (S_KL - S_KH));
            }
            MMAB(cs[2 * n2],     qfh[ks], kh[0], kh[1]);
            MMAB(cs[2 * n2 + 1], qfh[ks], kh[2], kh[3]);
            MMAB(cs[2 * n2],     qfh[ks], kl[0], kl[1]);
            MMAB(cs[2 * n2 + 1], qfh[ks], kl[2], kl[3]);
            MMAB(cs[2 * n2],     qfl[ks], kh[0], kh[1]);
            MMAB(cs[2 * n2 + 1], qfl[ks], kh[2], kh[3]);
        }

        // ---- online softmax (log2 units, ex2) ----
        float tA = cs[0][0], tB = cs[0][2];
#pragma unroll
        for (int t = 0; t < 8; ++t) {
            tA = fmaxf(tA, fmaxf(cs[t][0], cs[t][1]));
            tB = fmaxf(tB, fmaxf(cs[t][2], cs[t][3]));
        }
        tA = fmaxf(tA, __shfl_xor_sync(0xffffffffu, tA, 1));
        tA = fmaxf(tA, __shfl_xor_sync(0xffffffffu, tA, 2));
        tB = fmaxf(tB, __shfl_xor_sync(0xffffffffu, tB, 1));
        tB = fmaxf(tB, __shfl_xor_sync(0xffffffffu, tB, 2));
        float mnA = fmaxf(m0, tA), mnB = fmaxf(m1, tB);
        bool upd = (mnA != m0) || (mnB != m1);
        if (__any_sync(0xffffffffu, upd)) {
            float scA = ex2(m0 - mnA), scB = ex2(m1 - mnB);
            m0 = mnA; m1 = mnB;
            lsum0 *= scA; lsum1 *= scB;
#pragma unroll
            for (int nt = 0; nt < 16; ++nt) {
                co[nt][0] *= scA; co[nt][1] *= scA;
                co[nt][2] *= scB; co[nt][3] *= scB;
            }
        }

        uint32_t pf[4][4];
#pragma unroll
        for (int j = 0; j < 4; ++j) {
            float e0 = ex2(cs[2*j][0]   - mnA), e1 = ex2(cs[2*j][1]   - mnA);
            float e2 = ex2(cs[2*j][2]   - mnB), e3 = ex2(cs[2*j][3]   - mnB);
            float e4 = ex2(cs[2*j+1][0] - mnA), e5 = ex2(cs[2*j+1][1] - mnA);
            float e6 = ex2(cs[2*j+1][2] - mnB), e7 = ex2(cs[2*j+1][3] - mnB);
            lsum0 += (e0 + e1) + (e4 + e5);
            lsum1 += (e2 + e3) + (e6 + e7);
            pf[j][0] = pack_f16x2(e0, e1);
            pf[j][1] = pack_f16x2(e2, e3);
            pf[j][2] = pack_f16x2(e4, e5);
            pf[j][3] = pack_f16x2(e6, e7);
        }

        // ---- O += P V (fp16), V frags double-buffered ----
        uint32_t vA[4], vB[4];
        {
            uint32_t v0 = stg + S_V + (uint32_t)(b_row << 7) +
                          (uint32_t)((b_c8 ^ bxr) << 4);
            LDSM4(vA, v0);
        }
#pragma unroll
        for (int t = 0; t < 32; ++t) {
            const int j = t >> 3, n2 = t & 7;
            uint32_t* vf = (t & 1) ? vB : vA;
            if (t < 31) {
                const int tn = t + 1;
                const int jn = tn >> 3, n2n = tn & 7;
                uint32_t* vfn = (tn & 1) ? vB : vA;
                uint32_t vaddr = stg + S_V +
                                 (uint32_t)((n2n * 16 + b_row) << 7) +
                                 (uint32_t)(((2 * jn + b_c8) ^ bxr) << 4);
                LDSM4(vfn, vaddr);
            }
            MMAH(co[2 * n2],     pf[j], vf[0], vf[1]);
            MMAH(co[2 * n2 + 1], pf[j], vf[2], vf[3]);
        }

        // rotate ring
        uint32_t next = stg + STG_SZ;
        if (next >= sb + 3u * STG_SZ) next = sb;
        uint32_t nextpf = stg_pf + STG_SZ;
        if (nextpf >= sb + 3u * STG_SZ) nextpf = sb;
        stg = next;
        stg_pf = nextpf;
    }

    // ---- epilogue: reduce l within quads, divide, store ----
    lsum0 += __shfl_xor_sync(0xffffffffu, lsum0, 1);
    lsum0 += __shfl_xor_sync(0xffffffffu, lsum0, 2);
    lsum1 += __shfl_xor_sync(0xffffffffu, lsum1, 1);
    lsum1 += __shfl_xor_sync(0xffffffffu, lsum1, 2);
    float inv0 = 1.0f / lsum0;
    float inv1 = 1.0f / lsum1;

    float* o0 = Out + base + (size_t)(q0 + r0 + (lane >> 2)) * DH;
    float* o1 = o0 + 8 * DH;
    const int cb = (lane & 3) * 2;
#pragma unroll
    for (int nt = 0; nt < 16; ++nt) {
        int c = nt * 8 + cb;
        float2 w0 = make_float2(co[nt][0] * inv0, co[nt][1] * inv0);
        float2 w1 = make_float2(co[nt][2] * inv1, co[nt][3] * inv1);
        *reinterpret_cast<float2*>(o0 + c) = w0;
        *reinterpret_cast<float2*>(o1 + c) = w1;
    }
}

extern "C" void kernel_launch(void* const* d_in, const int* in_sizes, int n_in,
                              void* d_out, int out_size) {
    const float* Q = (const float*)d_in[0];
    const float* K = (const float*)d_in[1];
    const float* V = (const float*)d_in[2];
    float* O = (float*)d_out;

    unsigned short *qh, *ql, *kh, *kl, *vf;
    cudaGetSymbolAddress((void**)&qh, g_qhi);
    cudaGetSymbolAddress((void**)&ql, g_qlo);
    cudaGetSymbolAddress((void**)&kh, g_khi);
    cudaGetSymbolAddress((void**)&kl, g_klo);
    cudaGetSymbolAddress((void**)&vf, g_vf);

    split_qk_kernel<<<1024, 256>>>((const float4*)Q, (const float4*)K,
                                   qh, ql, kh, kl, NELEM / 4);
    v_transpose_kernel<<<dim3(SEQ / 32, DH / 32, HEADS), dim3(32, 8)>>>(V, vf);

    cudaFuncSetAttribute(fa_hmma_kernel,
                         cudaFuncAttributeMaxDynamicSharedMemorySize, SMEM_MAIN);
    dim3 grid(SEQ / BM, HEADS);
    fa_hmma_kernel<<<grid, NT, SMEM_MAIN>>>(O);
}

// round 9
// speedup vs baseline: 1.6299x; 1.1610x over previous
#include <cuda_runtime.h>
#include <cuda_bf16.h>
#include <cuda_fp16.h>
#include <cstdint>

#define HEADS 32
#define SEQ   2048
#define DH    128
#define BM    64
#define BN    64
#define NIT   (SEQ / BN)
#define NT    128
#define NELEM (HEADS * SEQ * DH)

// scratch (device globals: sanctioned scratch, no allocs)
__device__ __align__(16) unsigned short g_qhi[NELEM];   // Q*log2(e), bf16 hi
__device__ __align__(16) unsigned short g_qlo[NELEM];   // residual, bf16
__device__ __align__(16) unsigned short g_khi[NELEM];
__device__ __align__(16) unsigned short g_klo[NELEM];
__device__ __align__(16) unsigned short g_vf[NELEM];    // V^T [head][d][s], fp16

// 2-stage smem ring; stage: KH 16K, KL 16K, V 16K
#define STG_SZ  49152u
#define S_KH    0u
#define S_KL    16384u
#define S_V     32768u
#define SMEM_MAIN (2u * STG_SZ)   // 96KB per CTA -> 2 CTAs/SM

// ---------------- PTX helpers ----------------
__device__ __forceinline__ uint32_t smem_u32(const void* p) {
    uint32_t a;
    asm("{ .reg .u64 t; cvta.to.shared.u64 t, %1; cvt.u32.u64 %0, t; }" : "=r"(a) : "l"(p));
    return a;
}
__device__ __forceinline__ void cp16(uint32_t dst, const void* src) {
    asm volatile("cp.async.cg.shared.global [%0], [%1], 16;" :: "r"(dst), "l"(src) : "memory");
}
#define CP_COMMIT() asm volatile("cp.async.commit_group;" ::: "memory")
#define CP_WAIT_0() asm volatile("cp.async.wait_group 0;" ::: "memory")

#define LDSM4(r, a) \
    asm volatile("ldmatrix.sync.aligned.m8n8.x4.shared.b16 {%0,%1,%2,%3}, [%4];" \
        : "=r"((r)[0]), "=r"((r)[1]), "=r"((r)[2]), "=r"((r)[3]) : "r"(a))

#define MMAB(c, a, b0, b1) \
    asm volatile("mma.sync.aligned.m16n8k16.row.col.f32.bf16.bf16.f32 " \
        "{%0,%1,%2,%3}, {%4,%5,%6,%7}, {%8,%9}, {%0,%1,%2,%3};" \
        : "+f"((c)[0]), "+f"((c)[1]), "+f"((c)[2]), "+f"((c)[3]) \
        : "r"((a)[0]), "r"((a)[1]), "r"((a)[2]), "r"((a)[3]), "r"(b0), "r"(b1))

#define MMAH(c, a, b0, b1) \
    asm volatile("mma.sync.aligned.m16n8k16.row.col.f32.f16.f16.f32 " \
        "{%0,%1,%2,%3}, {%4,%5,%6,%7}, {%8,%9}, {%0,%1,%2,%3};" \
        : "+f"((c)[0]), "+f"((c)[1]), "+f"((c)[2]), "+f"((c)[3]) \
        : "r"((a)[0]), "r"((a)[1]), "r"((a)[2]), "r"((a)[3]), "r"(b0), "r"(b1))

__device__ __forceinline__ uint32_t pack_f16x2(float x, float y) {
    uint32_t d;
    asm("cvt.rn.f16x2.f32 %0, %1, %2;" : "=r"(d) : "f"(y), "f"(x));
    return d;
}
__device__ __forceinline__ float ex2(float x) {
    float r;
    asm("ex2.approx.f32 %0, %1;" : "=f"(r) : "f"(x));
    return r;
}

// ---------------- hi/lo split ----------------
__device__ __forceinline__ void split1(float v, unsigned short& h, unsigned short& l) {
    uint32_t b = __float_as_uint(v);
    h = (unsigned short)(b >> 16);
    float r = v - __uint_as_float(b & 0xffff0000u);
    l = __bfloat16_as_ushort(__float2bfloat16(r));
}

#define LOG2E 1.44269504088896340736f

__global__ void split_qk_kernel(const float4* __restrict__ Q, const float4* __restrict__ K,
                                unsigned short* __restrict__ qh, unsigned short* __restrict__ ql,
                                unsigned short* __restrict__ kh, unsigned short* __restrict__ kl,
                                int n4) {
    for (int i = blockIdx.x * blockDim.x + threadIdx.x; i < n4; i += gridDim.x * blockDim.x) {
        unsigned short h0,h1,h2,h3,l0,l1,l2,l3;
        float4 q = Q[i];
        split1(q.x * LOG2E, h0, l0); split1(q.y * LOG2E, h1, l1);
        split1(q.z * LOG2E, h2, l2); split1(q.w * LOG2E, h3, l3);
        *reinterpret_cast<uint2*>(qh + 4*(size_t)i) =
            make_uint2((uint32_t)h0 | ((uint32_t)h1<<16), (uint32_t)h2 | ((uint32_t)h3<<16));
        *reinterpret_cast<uint2*>(ql + 4*(size_t)i) =
            make_uint2((uint32_t)l0 | ((uint32_t)l1<<16), (uint32_t)l2 | ((uint32_t)l3<<16));
        float4 k = K[i];
        split1(k.x,h0,l0); split1(k.y,h1,l1); split1(k.z,h2,l2); split1(k.w,h3,l3);
        *reinterpret_cast<uint2*>(kh + 4*(size_t)i) =
            make_uint2((uint32_t)h0 | ((uint32_t)h1<<16), (uint32_t)h2 | ((uint32_t)h3<<16));
        *reinterpret_cast<uint2*>(kl + 4*(size_t)i) =
            make_uint2((uint32_t)l0 | ((uint32_t)l1<<16), (uint32_t)l2 | ((uint32_t)l3<<16));
    }
}

__global__ void v_transpose_kernel(const float* __restrict__ V,
                                   unsigned short* __restrict__ vf) {
    __shared__ float t[32][33];
    int h = blockIdx.z, s0 = blockIdx.x * 32, d0 = blockIdx.y * 32;
    int tx = threadIdx.x, ty = threadIdx.y;
    const float* src = V + ((size_t)h * SEQ + s0) * DH + d0;
#pragma unroll
    for (int j = 0; j < 32; j += 8)
        t[ty + j][tx] = src[(size_t)(ty + j) * DH + tx];
    __syncthreads();
#pragma unroll
    for (int j = 0; j < 32; j += 8) {
        __half hv = __float2half_rn(t[tx][ty + j]);
        size_t o = ((size_t)h * DH + d0 + ty + j) * SEQ + s0 + tx;
        vf[o] = *reinterpret_cast<unsigned short*>(&hv);
    }
}

// ---------------- stage loader (cp.async, swizzled), NT=128 ----------------
__device__ __forceinline__ void stage_load(uint32_t stg,
                                           const unsigned short* gkh, const unsigned short* gkl,
                                           const unsigned short* gv, int tid) {
#pragma unroll
    for (int t = 0; t < 8; ++t) {
        int idx = tid + t * NT;           // 0..1023
        int r = idx >> 4, c16 = idx & 15; // K: 64 rows x 16 chunks
        uint32_t d = stg + S_KH + ((uint32_t)r << 8) + (uint32_t)((c16 ^ (r & 7)) << 4);
        cp16(d, gkh + (size_t)r * DH + c16 * 8);
        cp16(d + (S_KL - S_KH), gkl + (size_t)r * DH + c16 * 8);
    }
#pragma unroll
    for (int t = 0; t < 8; ++t) {
        int idx = tid + t * NT;
        int r = idx >> 3, c16 = idx & 7;  // V^T: 128 rows x 8 chunks
        uint32_t d = stg + S_V + ((uint32_t)r << 7) + (uint32_t)((c16 ^ (r & 7)) << 4);
        cp16(d, gv + (size_t)r * SEQ + c16 * 8);
    }
}

// ---------------- main attention kernel ----------------
// 4 warps, pure M-partition: warp owns 16 query rows of the 64-row tile.
// 2 CTAs/SM: desynchronized CTAs overlap softmax with MMA across CTAs.
__global__ __launch_bounds__(NT, 2)
void fa_hmma_kernel(float* __restrict__ Out) {
    extern __shared__ char smc[];
    const uint32_t sb = smem_u32(smc);
    const int tid  = threadIdx.x;
    const int lane = tid & 31;
    const int warp = tid >> 5;
    const int head = blockIdx.y;
    const int q0   = blockIdx.x * BM;
    const size_t base = (size_t)head * SEQ * DH;

    const unsigned short* gqh = g_qhi + base + (size_t)q0 * DH;
    const unsigned short* gql = g_qlo + base + (size_t)q0 * DH;
    const unsigned short* gkh0 = g_khi + base;
    const unsigned short* gkl0 = g_klo + base;
    const unsigned short* gv0  = g_vf + (size_t)head * DH * SEQ;

    // ---- stage Q (64 rows, hi/lo) into buffer 0 area, hoist frags ----
    for (int idx = tid; idx < 1024; idx += NT) {
        int r = idx >> 4, c16 = idx & 15;
        uint32_t d = ((uint32_t)r << 8) + (uint32_t)((c16 ^ (r & 7)) << 4);
        *reinterpret_cast<uint4*>(smc + d) =
            *reinterpret_cast<const uint4*>(gqh + (size_t)r * DH + c16 * 8);
        *reinterpret_cast<uint4*>(smc + 16384u + d) =
            *reinterpret_cast<const uint4*>(gql + (size_t)r * DH + c16 * 8);
    }
    __syncthreads();

    const int r0    = warp * 16;
    const int a_row = r0 + (lane & 7) + ((lane >> 3) & 1) * 8;   // 0..63
    const int a_c8  = lane >> 4;
    const int axr   = a_row & 7;
    const int b_row = (lane & 7) + ((lane >> 4) << 3);
    const int b_c8  = (lane >> 3) & 1;
    const int bxr   = b_row & 7;

    uint32_t qfh[8][4], qfl[8][4];
#pragma unroll
    for (int ks = 0; ks < 8; ++ks) {
        uint32_t aaddr = sb + (uint32_t)(a_row << 8) +
                         (uint32_t)(((2 * ks + a_c8) ^ axr) << 4);
        LDSM4(qfh[ks], aaddr);
        LDSM4(qfl[ks], aaddr + 16384u);
    }
    __syncthreads();   // Q frags in regs; buffer 0 free for the ring

    // prologue: load stage 0
    stage_load(sb, gkh0, gkl0, gv0, tid);
    CP_COMMIT();

    float co[16][4];
#pragma unroll
    for (int i = 0; i < 16; ++i)
#pragma unroll
        for (int j = 0; j < 4; ++j) co[i][j] = 0.0f;
    float lsum0 = 0.0f, lsum1 = 0.0f;
    float m0 = -1e30f, m1 = -1e30f;

    for (int i = 0; i < NIT; ++i) {
        const uint32_t stg = sb + (uint32_t)(i & 1) * STG_SZ;
        const uint32_t stg_next = sb + (uint32_t)((i + 1) & 1) * STG_SZ;

        CP_WAIT_0();       // stage i complete (only pending group)
        __syncthreads();   // all warps done with compute(i-1) -> stg_next free

        if (i + 1 < NIT) {
            const int key0 = (i + 1) * BN;
            stage_load(stg_next, gkh0 + (size_t)key0 * DH, gkl0 + (size_t)key0 * DH,
                       gv0 + key0, tid);
            CP_COMMIT();
        }

        // ---- S = Q K^T (bf16 3-product hi/lo) ----
        float cs[8][4];
#pragma unroll
        for (int t = 0; t < 8; ++t)
#pragma unroll
            for (int j = 0; j < 4; ++j) cs[t][j] = 0.0f;

#pragma unroll
        for (int ks = 0; ks < 8; ++ks) {
#pragma unroll
            for (int n2 = 0; n2 < 4; ++n2) {
                uint32_t kh[4], kl[4];
                uint32_t baddr = stg + S_KH + (uint32_t)((n2 * 16 + b_row) << 8) +
                                 (uint32_t)(((2 * ks + b_c8) ^ bxr) << 4);
                LDSM4(kh, baddr);
                LDSM4(kl, baddr + (S_KL - S_KH));
                MMAB(cs[2 * n2],     qfh[ks], kh[0], kh[1]);
                MMAB(cs[2 * n2 + 1], qfh[ks], kh[2], kh[3]);
                MMAB(cs[2 * n2],     qfh[ks], kl[0], kl[1]);
                MMAB(cs[2 * n2 + 1], qfh[ks], kl[2], kl[3]);
                MMAB(cs[2 * n2],     qfl[ks], kh[0], kh[1]);
                MMAB(cs[2 * n2 + 1], qfl[ks], kh[2], kh[3]);
            }
        }

        // ---- online softmax (log2 units, ex2) ----
        float tA = cs[0][0], tB = cs[0][2];
#pragma unroll
        for (int t = 0; t < 8; ++t) {
            tA = fmaxf(tA, fmaxf(cs[t][0], cs[t][1]));
            tB = fmaxf(tB, fmaxf(cs[t][2], cs[t][3]));
        }
        tA = fmaxf(tA, __shfl_xor_sync(0xffffffffu, tA, 1));
        tA = fmaxf(tA, __shfl_xor_sync(0xffffffffu, tA, 2));
        tB = fmaxf(tB, __shfl_xor_sync(0xffffffffu, tB, 1));
        tB = fmaxf(tB, __shfl_xor_sync(0xffffffffu, tB, 2));
        float mnA = fmaxf(m0, tA), mnB = fmaxf(m1, tB);
        bool upd = (mnA != m0) || (mnB != m1);
        if (__any_sync(0xffffffffu, upd)) {
            float scA = ex2(m0 - mnA), scB = ex2(m1 - mnB);
            m0 = mnA; m1 = mnB;
            lsum0 *= scA; lsum1 *= scB;
#pragma unroll
            for (int nt = 0; nt < 16; ++nt) {
                co[nt][0] *= scA; co[nt][1] *= scA;
                co[nt][2] *= scB; co[nt][3] *= scB;
            }
        }

        uint32_t pf[4][4];
#pragma unroll
        for (int j = 0; j < 4; ++j) {
            float e0 = ex2(cs[2*j][0]   - mnA), e1 = ex2(cs[2*j][1]   - mnA);
            float e2 = ex2(cs[2*j][2]   - mnB), e3 = ex2(cs[2*j][3]   - mnB);
            float e4 = ex2(cs[2*j+1][0] - mnA), e5 = ex2(cs[2*j+1][1] - mnA);
            float e6 = ex2(cs[2*j+1][2] - mnB), e7 = ex2(cs[2*j+1][3] - mnB);
            lsum0 += (e0 + e1) + (e4 + e5);
            lsum1 += (e2 + e3) + (e6 + e7);
            pf[j][0] = pack_f16x2(e0, e1);
            pf[j][1] = pack_f16x2(e2, e3);
            pf[j][2] = pack_f16x2(e4, e5);
            pf[j][3] = pack_f16x2(e6, e7);
        }

        // ---- O += P V (single fp16 product) ----
#pragma unroll
        for (int j = 0; j < 4; ++j) {
#pragma unroll
            for (int n2 = 0; n2 < 8; ++n2) {
                uint32_t vf[4];
                uint32_t vaddr = stg + S_V + (uint32_t)((n2 * 16 + b_row) << 7) +
                                 (uint32_t)(((2 * j + b_c8) ^ bxr) << 4);
                LDSM4(vf, vaddr);
                MMAH(co[2 * n2],     pf[j], vf[0], vf[1]);
                MMAH(co[2 * n2 + 1], pf[j], vf[2], vf[3]);
            }
        }
    }

    // ---- epilogue: reduce l within quads, divide, store ----
    lsum0 += __shfl_xor_sync(0xffffffffu, lsum0, 1);
    lsum0 += __shfl_xor_sync(0xffffffffu, lsum0, 2);
    lsum1 += __shfl_xor_sync(0xffffffffu, lsum1, 1);
    lsum1 += __shfl_xor_sync(0xffffffffu, lsum1, 2);
    float inv0 = 1.0f / lsum0;
    float inv1 = 1.0f / lsum1;

    float* o0 = Out + base + (size_t)(q0 + r0 + (lane >> 2)) * DH;
    float* o1 = o0 + 8 * DH;
    const int cb = (lane & 3) * 2;
#pragma unroll
    for (int nt = 0; nt < 16; ++nt) {
        int c = nt * 8 + cb;
        float2 w0 = make_float2(co[nt][0] * inv0, co[nt][1] * inv0);
        float2 w1 = make_float2(co[nt][2] * inv1, co[nt][3] * inv1);
        *reinterpret_cast<float2*>(o0 + c) = w0;
        *reinterpret_cast<float2*>(o1 + c) = w1;
    }
}

extern "C" void kernel_launch(void* const* d_in, const int* in_sizes, int n_in,
                              void* d_out, int out_size) {
    const float* Q = (const float*)d_in[0];
    const float* K = (const float*)d_in[1];
    const float* V = (const float*)d_in[2];
    float* O = (float*)d_out;

    unsigned short *qh, *ql, *kh, *kl, *vf;
    cudaGetSymbolAddress((void**)&qh, g_qhi);
    cudaGetSymbolAddress((void**)&ql, g_qlo);
    cudaGetSymbolAddress((void**)&kh, g_khi);
    cudaGetSymbolAddress((void**)&kl, g_klo);
    cudaGetSymbolAddress((void**)&vf, g_vf);

    split_qk_kernel<<<1024, 256>>>((const float4*)Q, (const float4*)K,
                                   qh, ql, kh, kl, NELEM / 4);
    v_transpose_kernel<<<dim3(SEQ / 32, DH / 32, HEADS), dim3(32, 8)>>>(V, vf);

    cudaFuncSetAttribute(fa_hmma_kernel,
                         cudaFuncAttributeMaxDynamicSharedMemorySize, SMEM_MAIN);
    dim3 grid(SEQ / BM, HEADS);   // (32, 32) = 1024 CTAs, 2 per SM
    fa_hmma_kernel<<<grid, NT, SMEM_MAIN>>>(O);
}